// round 7
// baseline (speedup 1.0000x reference)
#include <cuda_runtime.h>
#include <cuda_fp16.h>
#include <cstdint>

// Problem constants
#define NB   16        // batch
#define CC   128       // channels
#define HH   112
#define WW   112
#define PLANE (HH*WW)          // 12544 pixels per plane
#define PTS   (98*16*16)       // 25088 sample points per image
#define THREADS 512
#define ITERS (PTS / THREADS)  // 49 exactly

static __device__ __forceinline__ unsigned int h2_bits(__half2 h)
{
    union { __half2 h; unsigned int u; } cvt;
    cvt.h = h;
    return cvt.u;
}

static __device__ __forceinline__ float2 bits_f2(unsigned int u)
{
    union { __half2 h; unsigned int u; } cvt;
    cvt.u = u;
    return __half22float2(cvt.h);
}

// smem: uint2 per pixel: e[p] = { h2(chA[p],chB[p]), h2(chA[p+1],chB[p+1]) }
// -> 12544 * 8 B = 100,352 B. One LDS.64 per corner-pair.
__global__ __launch_bounds__(THREADS, 2)
void patches_kernel(const float* __restrict__ fm,
                    const float* __restrict__ grid,
                    float* __restrict__ out)
{
    extern __shared__ uint2 e[];   // PLANE uint2

    const int n  = blockIdx.x >> 6;          // 16 images
    const int c0 = (blockIdx.x & 63) * 2;    // 64 channel pairs

    // ---- Stage: build x-paired half2 entries, conflict-free STS.128 ----
    {
        const float* __restrict__ pA = fm + ((size_t)n * CC + c0) * PLANE;
        const float* __restrict__ pB = pA + PLANE;
        uint4* __restrict__ ed = reinterpret_cast<uint4*>(e);
        for (int i = threadIdx.x; i < PLANE / 2; i += THREADS) {
            const int p0 = 2 * i;
            const float2 a01 = *reinterpret_cast<const float2*>(pA + p0);
            const float2 b01 = *reinterpret_cast<const float2*>(pB + p0);
            float a2 = 0.0f, b2 = 0.0f;
            if (p0 + 2 < PLANE) {           // guarded neighbor (entry never read)
                a2 = pA[p0 + 2];
                b2 = pB[p0 + 2];
            }
            const unsigned int h0 = h2_bits(__floats2half2_rn(a01.x, b01.x));
            const unsigned int h1 = h2_bits(__floats2half2_rn(a01.y, b01.y));
            const unsigned int h2v = h2_bits(__floats2half2_rn(a2, b2));
            uint4 v;                         // {e[p0], e[p0+1]}
            v.x = h0; v.y = h1;              // e[p0]   = (h0, h1)
            v.z = h1; v.w = h2v;             // e[p0+1] = (h1, h2)
            ed[i] = v;
        }
    }
    __syncthreads();

    // Per-thread pointers: pix = (tid & 255) loop-invariant; p advances by 2.
    const float2* __restrict__ g =
        reinterpret_cast<const float2*>(grid) + (size_t)n * PTS + threadIdx.x;

    // out[n, p, c, hg, wg]  flat = ((n*98 + p)*128 + c)*256 + pix
    float* __restrict__ o = out + (((size_t)n * 98) * CC + c0) * 256
                          + (size_t)(threadIdx.x >> 8) * (CC * 256)
                          + (threadIdx.x & 255);

    #pragma unroll 7
    for (int i = 0; i < ITERS; i++) {
        const float2 xy = g[(size_t)i * THREADS];

        // unnormalize (align_corners=False) + border clamp
        float x = fminf(fmaxf(fmaf(xy.x + 1.0f, 56.0f, -0.5f), 0.0f), 111.0f);
        float y = fminf(fmaxf(fmaf(xy.y + 1.0f, 56.0f, -0.5f), 0.0f), 111.0f);

        // corner clamped to [0,110]; wx in [0,1] (wx=1 reproduces border case)
        const int x0 = min((int)x, WW - 2);
        const int y0 = min((int)y, HH - 2);
        const float wx = x - (float)x0;
        const float wy = y - (float)y0;

        const int b00 = y0 * WW + x0;

        const uint2 row0 = e[b00];        // LDS.64: (q00, q01)
        const uint2 row1 = e[b00 + WW];   // LDS.64: (q10, q11)

        const float2 q00 = bits_f2(row0.x);
        const float2 q01 = bits_f2(row0.y);
        const float2 q10 = bits_f2(row1.x);
        const float2 q11 = bits_f2(row1.y);

        const float omwx = 1.0f - wx;
        const float omwy = 1.0f - wy;
        const float w00 = omwy * omwx;
        const float w01 = omwy * wx;
        const float w10 = wy * omwx;
        const float w11 = wy * wx;

        float r0 = q00.x * w00;
        float r1 = q00.y * w00;
        r0 = fmaf(q01.x, w01, r0);
        r1 = fmaf(q01.y, w01, r1);
        r0 = fmaf(q10.x, w10, r0);
        r1 = fmaf(q10.y, w10, r1);
        r0 = fmaf(q11.x, w11, r0);
        r1 = fmaf(q11.y, w11, r1);

        // each iteration advances p by THREADS/256 = 2 rows of [C,256]
        float* __restrict__ oi = o + (size_t)i * (2 * CC * 256);
        oi[0]   = r0;
        oi[256] = r1;
    }
}

extern "C" void kernel_launch(void* const* d_in, const int* in_sizes, int n_in,
                              void* d_out, int out_size)
{
    const float* fm   = (const float*)d_in[0];   // [16,128,112,112] f32
    const float* grid = (const float*)d_in[1];   // [16,98,16,16,2]  f32
    float* out        = (float*)d_out;           // [16,98,128,16,16] f32

    const int smem = PLANE * sizeof(uint2);      // 100,352 B
    cudaFuncSetAttribute(patches_kernel,
                         cudaFuncAttributeMaxDynamicSharedMemorySize, smem);

    const int blocks = NB * (CC / 2);            // 1024
    patches_kernel<<<blocks, THREADS, smem>>>(fm, grid, out);
}

// round 8
// speedup vs baseline: 1.1096x; 1.1096x over previous
#include <cuda_runtime.h>
#include <cuda_fp16.h>
#include <cstdint>

// Problem constants
#define NB   16        // batch
#define CC   128       // channels
#define HH   112
#define WW   112
#define PLANE (HH*WW)          // 12544 pixels per plane
#define PTS   (98*16*16)       // 25088 sample points per image
#define THREADS 512
#define ITERS (PTS / THREADS)  // 49 exactly

static __device__ __forceinline__ unsigned int h2_bits(__half2 h)
{
    union { __half2 h; unsigned int u; } cvt;
    cvt.h = h;
    return cvt.u;
}

// smem: one half2 per pixel packing channels (c0, c0+1) -> 50,176 B
// 4 blocks/SM -> 200,704 B smem, 64 warps/SM
__global__ __launch_bounds__(THREADS, 4)
void patches_kernel(const float* __restrict__ fm,
                    const float* __restrict__ grid,
                    float* __restrict__ out)
{
    extern __shared__ __half2 s[];   // PLANE half2

    const int n  = blockIdx.x >> 6;          // 16 images
    const int c0 = (blockIdx.x & 63) * 2;    // 64 channel pairs

    // ---- Stage 2 channel planes packed as half2 (LDG.128 x2 + STS.128) ----
    {
        const float4* __restrict__ pa =
            reinterpret_cast<const float4*>(fm + ((size_t)n * CC + c0) * PLANE);
        const float4* __restrict__ pb = pa + PLANE / 4;     // next channel plane
        uint4* __restrict__ sd = reinterpret_cast<uint4*>(s);
        #pragma unroll
        for (int i = threadIdx.x; i < PLANE / 4; i += THREADS) {
            const float4 a = pa[i];
            const float4 b = pb[i];
            uint4 v;
            v.x = h2_bits(__floats2half2_rn(a.x, b.x));
            v.y = h2_bits(__floats2half2_rn(a.y, b.y));
            v.z = h2_bits(__floats2half2_rn(a.z, b.z));
            v.w = h2_bits(__floats2half2_rn(a.w, b.w));
            sd[i] = v;
        }
    }
    __syncthreads();

    // Per-thread pointers: pix = (tid & 255) is loop-invariant; p advances by 2.
    const float2* __restrict__ g =
        reinterpret_cast<const float2*>(grid) + (size_t)n * PTS + threadIdx.x;

    // out[n, p, c, hg, wg]  flat = ((n*98 + p)*128 + c)*256 + pix
    float* __restrict__ o = out + (((size_t)n * 98) * CC + c0) * 256
                          + (threadIdx.x >> 8) * (CC * 256)
                          + (threadIdx.x & 255);

    #pragma unroll 7
    for (int i = 0; i < ITERS; i++) {
        const float2 xy = g[i * THREADS];          // 32-bit offset

        // unnormalize (align_corners=False) + border clamp
        float x = fminf(fmaxf(fmaf(xy.x + 1.0f, 56.0f, -0.5f), 0.0f), 111.0f);
        float y = fminf(fmaxf(fmaf(xy.y + 1.0f, 56.0f, -0.5f), 0.0f), 111.0f);

        // corner clamped to [0,110]; wx in [0,1] (wx=1 reproduces border case)
        const int x0 = min((int)x, WW - 2);
        const int y0 = min((int)y, HH - 2);
        const float wx = x - (float)x0;
        const float wy = y - (float)y0;

        const int b00 = y0 * WW + x0;

        const float2 q00 = __half22float2(s[b00]);
        const float2 q01 = __half22float2(s[b00 + 1]);
        const float2 q10 = __half22float2(s[b00 + WW]);
        const float2 q11 = __half22float2(s[b00 + WW + 1]);

        const float omwx = 1.0f - wx;
        const float omwy = 1.0f - wy;
        const float w00 = omwy * omwx;
        const float w01 = omwy * wx;
        const float w10 = wy * omwx;
        const float w11 = wy * wx;

        float r0 = q00.x * w00;
        float r1 = q00.y * w00;
        r0 = fmaf(q01.x, w01, r0);
        r1 = fmaf(q01.y, w01, r1);
        r0 = fmaf(q10.x, w10, r0);
        r1 = fmaf(q10.y, w10, r1);
        r0 = fmaf(q11.x, w11, r0);
        r1 = fmaf(q11.y, w11, r1);

        // each iteration advances p by THREADS/256 = 2 rows of [C,256]
        float* __restrict__ oi = o + i * (2 * CC * 256);   // 32-bit offset
        oi[0]   = r0;
        oi[256] = r1;
    }
}

extern "C" void kernel_launch(void* const* d_in, const int* in_sizes, int n_in,
                              void* d_out, int out_size)
{
    const float* fm   = (const float*)d_in[0];   // [16,128,112,112] f32
    const float* grid = (const float*)d_in[1];   // [16,98,16,16,2]  f32
    float* out        = (float*)d_out;           // [16,98,128,16,16] f32

    const int smem = PLANE * sizeof(__half2);    // 50,176 B
    cudaFuncSetAttribute(patches_kernel,
                         cudaFuncAttributeMaxDynamicSharedMemorySize, smem);

    const int blocks = NB * (CC / 2);            // 1024
    patches_kernel<<<blocks, THREADS, smem>>>(fm, grid, out);
}

// round 9
// speedup vs baseline: 1.2047x; 1.0857x over previous
#include <cuda_runtime.h>
#include <cuda_fp16.h>
#include <cstdint>

// Problem constants
#define NB   16        // batch
#define CC   128       // channels
#define HH   112
#define WW   112
#define PLANE (HH*WW)          // 12544 pixels per plane
#define PTS   (98*16*16)       // 25088 sample points per image
#define THREADS 512
#define ITERS (PTS / THREADS)  // 49 exactly

static __device__ __forceinline__ unsigned int h2_bits(__half2 h)
{
    union { __half2 h; unsigned int u; } cvt;
    cvt.h = h;
    return cvt.u;
}

// smem: one half2 per pixel packing channels (c0, c0+1) -> 50,176 B
__global__ __launch_bounds__(THREADS, 3)
void patches_kernel(const float* __restrict__ fm,
                    const float* __restrict__ grid,
                    float* __restrict__ out)
{
    extern __shared__ __half2 s[];   // PLANE half2

    const int n  = blockIdx.x >> 6;          // 16 images
    const int c0 = (blockIdx.x & 63) * 2;    // 64 channel pairs

    // ---- Stage 2 channel planes packed as half2 (LDG.128 x2 + STS.128) ----
    {
        const float4* __restrict__ pa =
            reinterpret_cast<const float4*>(fm + ((size_t)n * CC + c0) * PLANE);
        const float4* __restrict__ pb = pa + PLANE / 4;     // next channel plane
        uint4* __restrict__ sd = reinterpret_cast<uint4*>(s);
        #pragma unroll
        for (int i = threadIdx.x; i < PLANE / 4; i += THREADS) {
            const float4 a = pa[i];
            const float4 b = pb[i];
            uint4 v;
            v.x = h2_bits(__floats2half2_rn(a.x, b.x));
            v.y = h2_bits(__floats2half2_rn(a.y, b.y));
            v.z = h2_bits(__floats2half2_rn(a.z, b.z));
            v.w = h2_bits(__floats2half2_rn(a.w, b.w));
            sd[i] = v;
        }
    }
    __syncthreads();

    // Per-thread pointers: pix = (tid & 255) is loop-invariant; p advances by 2.
    const float2* __restrict__ g =
        reinterpret_cast<const float2*>(grid) + (size_t)n * PTS + threadIdx.x;

    // out[n, p, c, hg, wg]  flat = ((n*98 + p)*128 + c)*256 + pix
    float* __restrict__ o = out + (((size_t)n * 98) * CC + c0) * 256
                          + (threadIdx.x >> 8) * (CC * 256)
                          + (threadIdx.x & 255);

    #pragma unroll 7
    for (int i = 0; i < ITERS; i++) {
        const float2 xy = g[i * THREADS];

        // unnormalize (align_corners=False) + border clamp
        float x = fminf(fmaxf(fmaf(xy.x + 1.0f, 56.0f, -0.5f), 0.0f), 111.0f);
        float y = fminf(fmaxf(fmaf(xy.y + 1.0f, 56.0f, -0.5f), 0.0f), 111.0f);

        // corner clamped to [0,110]; wx in [0,1] (wx=1 reproduces border case)
        const int x0 = min((int)x, WW - 2);
        const int y0 = min((int)y, HH - 2);
        const float wx = x - (float)x0;
        const float wy = y - (float)y0;

        const int b00 = y0 * WW + x0;

        const __half2 q00 = s[b00];
        const __half2 q01 = s[b00 + 1];
        const __half2 q10 = s[b00 + WW];
        const __half2 q11 = s[b00 + WW + 1];

        // packed fp16 bilinear lerp: 3x HSUB2 + 3x HFMA2
        const __half2 wx2 = __float2half2_rn(wx);
        const __half2 wy2 = __float2half2_rn(wy);
        const __half2 top = __hfma2(wx2, __hsub2(q01, q00), q00);
        const __half2 bot = __hfma2(wx2, __hsub2(q11, q10), q10);
        const __half2 res = __hfma2(wy2, __hsub2(bot, top), top);

        const float2 r = __half22float2(res);

        // each iteration advances p by THREADS/256 = 2 rows of [C,256]
        float* __restrict__ oi = o + i * (2 * CC * 256);
        oi[0]   = r.x;
        oi[256] = r.y;
    }
}

extern "C" void kernel_launch(void* const* d_in, const int* in_sizes, int n_in,
                              void* d_out, int out_size)
{
    const float* fm   = (const float*)d_in[0];   // [16,128,112,112] f32
    const float* grid = (const float*)d_in[1];   // [16,98,16,16,2]  f32
    float* out        = (float*)d_out;           // [16,98,128,16,16] f32

    const int smem = PLANE * sizeof(__half2);    // 50,176 B
    cudaFuncSetAttribute(patches_kernel,
                         cudaFuncAttributeMaxDynamicSharedMemorySize, smem);

    const int blocks = NB * (CC / 2);            // 1024
    patches_kernel<<<blocks, THREADS, smem>>>(fm, grid, out);
}